// round 15
// baseline (speedup 1.0000x reference)
#include <cuda_runtime.h>
#include <math.h>

// Problem constants
#define T_TOKENS 25088      // 8 * 3136
#define DMODEL   768
#define NHEAD    12
#define DHEAD    64
#define FFDIM    3072
#define WS2      49
#define NWIN     512        // T_TOKENS / 49
#define D3       2304       // 3 * DMODEL

// ---------------- scratch (device globals; no allocation allowed) ----------------
__device__ __align__(128) float g_h[(size_t)T_TOKENS * DMODEL];
// fp16 planes
__device__ __align__(128) unsigned short g_qkvh[(size_t)T_TOKENS * D3];
__device__ __align__(128) unsigned short g_yh[(size_t)T_TOKENS * DMODEL];
__device__ __align__(128) unsigned short g_oh[(size_t)T_TOKENS * DMODEL];
__device__ __align__(128) unsigned short g_fh[(size_t)T_TOKENS * FFDIM];
__device__ __align__(128) unsigned short g_wh[(size_t)FFDIM * DMODEL];

// ---------------- fp16 helpers (inline PTX; no cuda_fp16.h) ----------------
__device__ __forceinline__ unsigned short f2h(float f)
{
    unsigned short h;
    asm("cvt.rn.f16.f32 %0, %1;" : "=h"(h) : "f"(f));
    return h;
}

// ---------------- weight convert: fp32 -> fp16 plane ----------------
__global__ __launch_bounds__(256) void cvt_kernel(
    const float* __restrict__ src, unsigned short* __restrict__ dst)
{
    const int i = (blockIdx.x * 256 + threadIdx.x) * 4;
    float4 v = *(const float4*)(src + i);
    unsigned p0 = (unsigned)f2h(v.x) | ((unsigned)f2h(v.y) << 16);
    unsigned p1 = (unsigned)f2h(v.z) | ((unsigned)f2h(v.w) << 16);
    uint2 o;
    o.x = p0;
    o.y = p1;
    *(uint2*)(dst + i) = o;
}

// ---------------- LayerNorm: one block per token; writes fp16 plane ---------------
__global__ __launch_bounds__(256) void ln_kernel(
    const float* __restrict__ x, const float* __restrict__ w,
    const float* __restrict__ b, unsigned short* __restrict__ yh)
{
    const int t = blockIdx.x;
    const float* xr = x + (size_t)t * DMODEL;
    unsigned short* yhr = yh + (size_t)t * DMODEL;
    const int tid = threadIdx.x;

    float v0 = xr[tid];
    float v1 = xr[tid + 256];
    float v2 = xr[tid + 512];
    float s = v0 + v1 + v2;
    float q = v0 * v0 + v1 * v1 + v2 * v2;

    #pragma unroll
    for (int off = 16; off > 0; off >>= 1) {
        s += __shfl_xor_sync(0xFFFFFFFFu, s, off);
        q += __shfl_xor_sync(0xFFFFFFFFu, q, off);
    }
    __shared__ float ss[8], sq[8];
    const int wid = tid >> 5, lid = tid & 31;
    if (lid == 0) { ss[wid] = s; sq[wid] = q; }
    __syncthreads();
    if (tid == 0) {
        float S = 0.f, Q = 0.f;
        #pragma unroll
        for (int i = 0; i < 8; i++) { S += ss[i]; Q += sq[i]; }
        float m = S * (1.0f / DMODEL);
        float var = Q * (1.0f / DMODEL) - m * m;
        ss[0] = m;
        sq[0] = rsqrtf(var + 1e-5f);
    }
    __syncthreads();
    const float m = ss[0], r = sq[0];
    float o0 = (v0 - m) * r * w[tid]       + b[tid];
    float o1 = (v1 - m) * r * w[tid + 256] + b[tid + 256];
    float o2 = (v2 - m) * r * w[tid + 512] + b[tid + 512];
    yhr[tid]       = f2h(o0);
    yhr[tid + 256] = f2h(o1);
    yhr[tid + 512] = f2h(o2);
}

// ---------------- asm helpers ----------------
__device__ __forceinline__ unsigned smem_u32(const void* p)
{
    unsigned a;
    asm volatile("{ .reg .u64 t; cvta.to.shared.u64 t, %1; cvt.u32.u64 %0, t; }"
                 : "=r"(a) : "l"(p));
    return a;
}

__device__ __forceinline__ void ldsm4a(unsigned* r, unsigned addr)
{
    asm volatile("ldmatrix.sync.aligned.m8n8.x4.shared.b16 {%0,%1,%2,%3}, [%4];"
                 : "=r"(r[0]), "=r"(r[1]), "=r"(r[2]), "=r"(r[3]) : "r"(addr));
}

__device__ __forceinline__ void mma_f16(float* c, const unsigned* a, unsigned b0, unsigned b1)
{
    asm volatile("mma.sync.aligned.m16n8k16.row.col.f32.f16.f16.f32 "
                 "{%0,%1,%2,%3}, {%4,%5,%6,%7}, {%8,%9}, {%0,%1,%2,%3};"
                 : "+f"(c[0]), "+f"(c[1]), "+f"(c[2]), "+f"(c[3])
                 : "r"(a[0]), "r"(a[1]), "r"(a[2]), "r"(a[3]), "r"(b0), "r"(b1));
}

__device__ __forceinline__ void cp16(unsigned dst, const void* src)
{
    asm volatile("cp.async.cg.shared.global [%0], [%1], 16;"
                 :: "r"(dst), "l"(src) : "memory");
}

__device__ __forceinline__ void cp_commit()
{
    asm volatile("cp.async.commit_group;" ::: "memory");
}

__device__ __forceinline__ void cp_wait1()
{
    asm volatile("cp.async.wait_group 1;" ::: "memory");
}

__device__ __forceinline__ void cp_wait0()
{
    asm volatile("cp.async.wait_group 0;" ::: "memory");
}

// ---------------- Windowed attention (tensor-core, fp16 end-to-end) ----------------
// One block per (window, head), 128 threads = 4 warps. Tiles padded to 64.
// smem: Q, K, Vt, P fp16 64x72-half rows (144B); S fp32 56x60.
#define HROWB 144
#define QOFF  0
#define KOFF  9216
#define VTOFF 18432
#define POFF  27648
#define SOFF  36864
#define SSTR  60
#define ATTN_SMEM (36864 + 56 * SSTR * 4)   // 50304 bytes

__global__ __launch_bounds__(128) void attn_kernel(
    const unsigned short* __restrict__ qkv, unsigned short* __restrict__ oh)
{
    extern __shared__ unsigned char hsm[];
    const unsigned sbase = smem_u32(hsm);
    const int w  = blockIdx.x / NHEAD;
    const int hd = blockIdx.x % NHEAD;
    const int t0 = w * WS2;
    const int tid = threadIdx.x;
    const int lane = tid & 31;
    const int wi = tid >> 5;

    // zero the fp16 regions (Q,K,Vt,P = 36864 bytes = 2304 uint4)
    {
        uint4 z;
        z.x = 0; z.y = 0; z.z = 0; z.w = 0;
        for (int i = tid; i < 2304; i += 128)
            ((uint4*)hsm)[i] = z;
    }
    __syncthreads();

    // load q,k rows; v transposed (49 rows x 8 chunks of 8 halves)
    for (int i = tid; i < WS2 * 8; i += 128) {
        int r = i >> 3;
        int c8 = (i & 7) * 8;
        size_t base = (size_t)(t0 + r) * D3 + hd * DHEAD + c8;
        uint4 qu = *(const uint4*)(qkv + base);
        uint4 ku = *(const uint4*)(qkv + base + DMODEL);
        uint4 vu = *(const uint4*)(qkv + base + 2 * DMODEL);
        *(uint4*)(hsm + QOFF + r * HROWB + c8 * 2) = qu;
        *(uint4*)(hsm + KOFF + r * HROWB + c8 * 2) = ku;
        const unsigned short* vp = (const unsigned short*)&vu;
        #pragma unroll
        for (int e = 0; e < 8; e++)
            *(unsigned short*)(hsm + VTOFF + (c8 + e) * HROWB + r * 2) = vp[e];
    }
    __syncthreads();

    float* sS = (float*)(hsm + SOFF);

    // phase 1: S = Q @ K^T (warp wi: rows 16*wi..16*wi+15, all 64 cols)
    {
        float acc[8][4];
        #pragma unroll
        for (int i = 0; i < 8; i++)
            #pragma unroll
            for (int j = 0; j < 4; j++) acc[i][j] = 0.f;
        #pragma unroll
        for (int ks = 0; ks < 4; ks++) {
            unsigned aq[4];
            ldsm4a(aq, sbase + QOFF + (wi * 16 + (lane & 15)) * HROWB
                       + ks * 32 + ((lane >> 4) << 4));
            unsigned bk[4][4];
            #pragma unroll
            for (int nb = 0; nb < 4; nb++)
                ldsm4a(bk[nb], sbase + KOFF + (nb * 16 + (lane & 15)) * HROWB
                               + ks * 32 + ((lane >> 4) << 4));
            #pragma unroll
            for (int nt = 0; nt < 8; nt++)
                mma_f16(acc[nt], aq, bk[nt >> 1][nt & 1], bk[nt >> 1][(nt & 1) + 2]);
        }
        #pragma unroll
        for (int nt = 0; nt < 8; nt++) {
            #pragma unroll
            for (int half = 0; half < 2; half++) {
                int row = wi * 16 + (lane >> 2) + half * 8;
                int col = nt * 8 + (lane & 3) * 2;
                if (row < 56 && col < 56) {
                    sS[row * SSTR + col]     = acc[nt][half * 2 + 0] * 0.125f;
                    sS[row * SSTR + col + 1] = acc[nt][half * 2 + 1] * 0.125f;
                }
            }
        }
    }
    __syncthreads();

    // softmax (4 warps, one row per warp iteration), write fp16 P
    {
        unsigned short* sP = (unsigned short*)(hsm + POFF);
        for (int r = wi; r < WS2; r += 4) {
            float v1 = (lane < WS2)      ? sS[r * SSTR + lane]      : -1e30f;
            float v2 = (lane + 32 < WS2) ? sS[r * SSTR + 32 + lane] : -1e30f;
            float mx = fmaxf(v1, v2);
            #pragma unroll
            for (int off = 16; off > 0; off >>= 1)
                mx = fmaxf(mx, __shfl_xor_sync(0xFFFFFFFFu, mx, off));
            float e1 = (lane < WS2)      ? __expf(v1 - mx) : 0.f;
            float e2 = (lane + 32 < WS2) ? __expf(v2 - mx) : 0.f;
            float sum = e1 + e2;
            #pragma unroll
            for (int off = 16; off > 0; off >>= 1)
                sum += __shfl_xor_sync(0xFFFFFFFFu, sum, off);
            float inv = 1.0f / sum;
            if (lane < WS2)      sP[r * 72 + lane]      = f2h(e1 * inv);
            if (lane + 32 < WS2) sP[r * 72 + 32 + lane] = f2h(e2 * inv);
        }
    }
    __syncthreads();

    // phase 2: O = P @ Vt^T (A = P [rows, j], B = Vt [d, j]; j padded with zeros)
    {
        float acc[8][4];
        #pragma unroll
        for (int i = 0; i < 8; i++)
            #pragma unroll
            for (int j = 0; j < 4; j++) acc[i][j] = 0.f;
        #pragma unroll
        for (int ks = 0; ks < 4; ks++) {
            unsigned ap[4];
            ldsm4a(ap, sbase + POFF + (wi * 16 + (lane & 15)) * HROWB
                       + ks * 32 + ((lane >> 4) << 4));
            unsigned bv[4][4];
            #pragma unroll
            for (int nb = 0; nb < 4; nb++)
                ldsm4a(bv[nb], sbase + VTOFF + (nb * 16 + (lane & 15)) * HROWB
                               + ks * 32 + ((lane >> 4) << 4));
            #pragma unroll
            for (int nt = 0; nt < 8; nt++)
                mma_f16(acc[nt], ap, bv[nt >> 1][nt & 1], bv[nt >> 1][(nt & 1) + 2]);
        }
        #pragma unroll
        for (int nt = 0; nt < 8; nt++) {
            #pragma unroll
            for (int half = 0; half < 2; half++) {
                int row = wi * 16 + (lane >> 2) + half * 8;
                int col = nt * 8 + (lane & 3) * 2;
                if (row < WS2) {
                    unsigned p = (unsigned)f2h(acc[nt][half * 2 + 0])
                               | ((unsigned)f2h(acc[nt][half * 2 + 1]) << 16);
                    *(unsigned*)(oh + (size_t)(t0 + row) * DMODEL + hd * DHEAD + col) = p;
                }
            }
        }
    }
}

// ---------------- fp16 tensor-core GEMM (cp.async 2-stage, K-chunk 64) -------------
// C = act(A @ B^T + bias) (+ res); fp16 A [M,K], B [N,K]; block 128x128, K-chunk 64.
// 8 warps, warp tile 64x32, mma.m16n8k16.f16; smem rows 144B (128B data + 16B pad).
#define ROWB 144
#define PLANEB (128 * ROWB)          // 18432
#define STAGEB (2 * PLANEB)          // 36864 (A plane + B plane)
#define NSTAGE 2
#define SMEMB  (NSTAGE * STAGEB)     // 73728

template <bool GELU, bool RES, bool HALFOUT>
__global__ __launch_bounds__(256) void gemm_f16(
    const unsigned short* __restrict__ Ah,
    const unsigned short* __restrict__ Bh,
    const float* __restrict__ bias,
    const float* __restrict__ res,
    float* __restrict__ C,
    unsigned short* __restrict__ Ch,
    int N, int K)
{
    extern __shared__ unsigned char dsm[];
    const unsigned sbase = smem_u32(dsm);
    const int tid = threadIdx.x;
    const int lane = tid & 31;
    const int wid = tid >> 5;
    const int wm = wid & 1;
    const int wn = wid >> 1;
    const int bm = blockIdx.y * 128;
    const int bn = blockIdx.x * 128;

    float acc[4][4][4];
    #pragma unroll
    for (int i = 0; i < 4; i++)
        #pragma unroll
        for (int j = 0; j < 4; j++)
            #pragma unroll
            for (int k = 0; k < 4; k++) acc[i][j][k] = 0.f;

    // loader: rows r0 and r0+64; two 16B chunks (ch*2, ch*2+1) of the 128B row
    const int r0 = tid >> 2;            // 0..63
    const int ch = tid & 3;             // 0..3
    const unsigned short* gA = Ah + (size_t)(bm + r0) * K + ch * 16;
    const unsigned short* gB = Bh + (size_t)(bn + r0) * K + ch * 16;
    const size_t rstep = (size_t)64 * K;
    const unsigned da0 = r0 * ROWB + ch * 32;
    const unsigned da1 = (r0 + 64) * ROWB + ch * 32;
    const int nkc = K / 64;

    // prologue: stage 0, chunk 0
    {
        const unsigned st = sbase;
        cp16(st + da0,               gA);
        cp16(st + da0 + 16,          gA + 8);
        cp16(st + da1,               gA + rstep);
        cp16(st + da1 + 16,          gA + rstep + 8);
        cp16(st + PLANEB + da0,      gB);
        cp16(st + PLANEB + da0 + 16, gB + 8);
        cp16(st + PLANEB + da1,      gB + rstep);
        cp16(st + PLANEB + da1 + 16, gB + rstep + 8);
        cp_commit();
    }

    for (int kc = 0; kc < nkc; kc++) {
        if (kc + 1 < nkc) {
            const unsigned st = sbase + ((kc + 1) & 1) * STAGEB;
            const int ko = (kc + 1) * 64;
            cp16(st + da0,               gA + ko);
            cp16(st + da0 + 16,          gA + ko + 8);
            cp16(st + da1,               gA + ko + rstep);
            cp16(st + da1 + 16,          gA + ko + rstep + 8);
            cp16(st + PLANEB + da0,      gB + ko);
            cp16(st + PLANEB + da0 + 16, gB + ko + 8);
            cp16(st + PLANEB + da1,      gB + ko + rstep);
            cp16(st + PLANEB + da1 + 16, gB + ko + rstep + 8);
            cp_commit();
            cp_wait1();
        } else {
            cp_wait0();
        }
        __syncthreads();

        const unsigned st = sbase + (kc & 1) * STAGEB;
        #pragma unroll
        for (int ks = 0; ks < 4; ks++) {
            const unsigned abase = st + (wm * 64 + (lane & 15)) * ROWB
                                   + ks * 32 + ((lane >> 4) << 4);
            const unsigned bbase = st + PLANEB + (wn * 32 + (lane & 15)) * ROWB
                                   + ks * 32 + ((lane >> 4) << 4);
            unsigned ah[4][4];
            #pragma unroll
            for (int mi = 0; mi < 4; mi++)
                ldsm4a(ah[mi], abase + mi * 16 * ROWB);
            unsigned bh[2][4];
            #pragma unroll
            for (int nj = 0; nj < 2; nj++)
                ldsm4a(bh[nj], bbase + nj * 16 * ROWB);
            #pragma unroll
            for (int mi = 0; mi < 4; mi++)
                #pragma unroll
                for (int ni = 0; ni < 4; ni++)
                    mma_f16(acc[mi][ni], ah[mi], bh[ni >> 1][ni & 1],
                            bh[ni >> 1][(ni & 1) + 2]);
        }
        __syncthreads();
    }

    // epilogue
    #pragma unroll
    for (int mi = 0; mi < 4; mi++) {
        #pragma unroll
        for (int ni = 0; ni < 4; ni++) {
            const int col = bn + wn * 32 + ni * 8 + (lane & 3) * 2;
            const float bs0 = bias[col];
            const float bs1 = bias[col + 1];
            #pragma unroll
            for (int half = 0; half < 2; half++) {
                const int row = bm + wm * 64 + mi * 16 + (lane >> 2) + half * 8;
                float v0 = acc[mi][ni][half * 2 + 0] + bs0;
                float v1 = acc[mi][ni][half * 2 + 1] + bs1;
                if (GELU) {
                    v0 = 0.5f * v0 * (1.0f + erff(v0 * 0.70710678118654752f));
                    v1 = 0.5f * v1 * (1.0f + erff(v1 * 0.70710678118654752f));
                }
                if (RES) {
                    float2 r2 = *(const float2*)(res + (size_t)row * N + col);
                    v0 += r2.x;
                    v1 += r2.y;
                }
                if (HALFOUT) {
                    unsigned p = (unsigned)f2h(v0) | ((unsigned)f2h(v1) << 16);
                    *(unsigned*)(Ch + (size_t)row * N + col) = p;
                } else {
                    float2 o2;
                    o2.x = v0;
                    o2.y = v1;
                    *(float2*)(C + (size_t)row * N + col) = o2;
                }
            }
        }
    }
}

// ---------------- host-side launch ----------------
extern "C" void kernel_launch(void* const* d_in, const int* in_sizes, int n_in,
                              void* d_out, int out_size)
{
    const float* x     = (const float*)d_in[0];
    const float* Wqkv  = (const float*)d_in[1];
    const float* bqkv  = (const float*)d_in[2];
    const float* Wo    = (const float*)d_in[3];
    const float* bo    = (const float*)d_in[4];
    const float* ln1_w = (const float*)d_in[5];
    const float* ln1_b = (const float*)d_in[6];
    const float* W1    = (const float*)d_in[7];
    const float* b1    = (const float*)d_in[8];
    const float* W2    = (const float*)d_in[9];
    const float* b2    = (const float*)d_in[10];
    const float* ln2_w = (const float*)d_in[11];
    const float* ln2_b = (const float*)d_in[12];
    float* out = (float*)d_out;

    static float *p_h = nullptr;
    static unsigned short *p_qkvh = nullptr, *p_yh = nullptr, *p_oh = nullptr;
    static unsigned short *p_fh = nullptr, *p_wh = nullptr;
    if (!p_h) {
        cudaGetSymbolAddress((void**)&p_h,    g_h);
        cudaGetSymbolAddress((void**)&p_qkvh, g_qkvh);
        cudaGetSymbolAddress((void**)&p_yh,   g_yh);
        cudaGetSymbolAddress((void**)&p_oh,   g_oh);
        cudaGetSymbolAddress((void**)&p_fh,   g_fh);
        cudaGetSymbolAddress((void**)&p_wh,   g_wh);
        cudaFuncSetAttribute(gemm_f16<false, false, true>,
                             cudaFuncAttributeMaxDynamicSharedMemorySize, SMEMB);
        cudaFuncSetAttribute(gemm_f16<false, true, false>,
                             cudaFuncAttributeMaxDynamicSharedMemorySize, SMEMB);
        cudaFuncSetAttribute(gemm_f16<true, false, true>,
                             cudaFuncAttributeMaxDynamicSharedMemorySize, SMEMB);
        cudaFuncSetAttribute(attn_kernel,
                             cudaFuncAttributeMaxDynamicSharedMemorySize, ATTN_SMEM);
    }

    const dim3 blk(256);
    const dim3 ablk(128);
    const dim3 grid_qkv(D3 / 128,     T_TOKENS / 128);
    const dim3 grid_d  (DMODEL / 128, T_TOKENS / 128);
    const dim3 grid_ff (FFDIM / 128,  T_TOKENS / 128);

    for (int l = 0; l < 2; l++) {
        const float* hin  = (l == 0) ? x : p_h;
        float* hout2 = (l == 1) ? out : p_h;   // last FFN GEMM writes final output

        // pre-norm attention
        ln_kernel<<<T_TOKENS, blk>>>(hin, ln1_w + l * DMODEL, ln1_b + l * DMODEL, p_yh);
        cvt_kernel<<<(D3 * DMODEL) / 1024, blk>>>(Wqkv + (size_t)l * D3 * DMODEL, p_wh);
        gemm_f16<false, false, true><<<grid_qkv, blk, SMEMB>>>(
            p_yh, p_wh, bqkv + (size_t)l * D3,
            nullptr, nullptr, p_qkvh, D3, DMODEL);
        attn_kernel<<<NWIN * NHEAD, ablk, ATTN_SMEM>>>(p_qkvh, p_oh);
        cvt_kernel<<<(DMODEL * DMODEL) / 1024, blk>>>(Wo + (size_t)l * DMODEL * DMODEL, p_wh);
        gemm_f16<false, true, false><<<grid_d, blk, SMEMB>>>(
            p_oh, p_wh, bo + (size_t)l * DMODEL,
            hin, p_h, nullptr, DMODEL, DMODEL);

        // pre-norm FFN
        ln_kernel<<<T_TOKENS, blk>>>(p_h, ln2_w + l * DMODEL, ln2_b + l * DMODEL, p_yh);
        cvt_kernel<<<(FFDIM * DMODEL) / 1024, blk>>>(W1 + (size_t)l * FFDIM * DMODEL, p_wh);
        gemm_f16<true, false, true><<<grid_ff, blk, SMEMB>>>(
            p_yh, p_wh, b1 + (size_t)l * FFDIM,
            nullptr, nullptr, p_fh, FFDIM, DMODEL);
        cvt_kernel<<<(DMODEL * FFDIM) / 1024, blk>>>(W2 + (size_t)l * DMODEL * FFDIM, p_wh);
        gemm_f16<false, true, false><<<grid_d, blk, SMEMB>>>(
            p_fh, p_wh, b2 + (size_t)l * DMODEL,
            p_h, hout2, nullptr, DMODEL, FFDIM);
    }
    (void)in_sizes; (void)n_in; (void)out_size;
}

// round 16
// speedup vs baseline: 1.0272x; 1.0272x over previous
#include <cuda_runtime.h>
#include <math.h>

// Problem constants
#define T_TOKENS 25088      // 8 * 3136
#define DMODEL   768
#define NHEAD    12
#define DHEAD    64
#define FFDIM    3072
#define WS2      49
#define NWIN     512        // T_TOKENS / 49
#define D3       2304       // 3 * DMODEL

// ---------------- scratch (device globals; no allocation allowed) ----------------
__device__ __align__(128) float g_h[(size_t)T_TOKENS * DMODEL];
// fp16 planes
__device__ __align__(128) unsigned short g_qkvh[(size_t)T_TOKENS * D3];
__device__ __align__(128) unsigned short g_yh[(size_t)T_TOKENS * DMODEL];
__device__ __align__(128) unsigned short g_oh[(size_t)T_TOKENS * DMODEL];
__device__ __align__(128) unsigned short g_fh[(size_t)T_TOKENS * FFDIM];
__device__ __align__(128) unsigned short g_wh[(size_t)FFDIM * DMODEL];

// ---------------- fp16 helpers (inline PTX; no cuda_fp16.h) ----------------
__device__ __forceinline__ unsigned short f2h(float f)
{
    unsigned short h;
    asm("cvt.rn.f16.f32 %0, %1;" : "=h"(h) : "f"(f));
    return h;
}

// ---------------- weight convert: fp32 -> fp16 plane ----------------
__global__ __launch_bounds__(256) void cvt_kernel(
    const float* __restrict__ src, unsigned short* __restrict__ dst)
{
    const int i = (blockIdx.x * 256 + threadIdx.x) * 4;
    float4 v = *(const float4*)(src + i);
    unsigned p0 = (unsigned)f2h(v.x) | ((unsigned)f2h(v.y) << 16);
    unsigned p1 = (unsigned)f2h(v.z) | ((unsigned)f2h(v.w) << 16);
    uint2 o;
    o.x = p0;
    o.y = p1;
    *(uint2*)(dst + i) = o;
}

// ---------------- LayerNorm: one block per token; writes fp16 plane ---------------
__global__ __launch_bounds__(256) void ln_kernel(
    const float* __restrict__ x, const float* __restrict__ w,
    const float* __restrict__ b, unsigned short* __restrict__ yh)
{
    const int t = blockIdx.x;
    const float* xr = x + (size_t)t * DMODEL;
    unsigned short* yhr = yh + (size_t)t * DMODEL;
    const int tid = threadIdx.x;

    float v0 = xr[tid];
    float v1 = xr[tid + 256];
    float v2 = xr[tid + 512];
    float s = v0 + v1 + v2;
    float q = v0 * v0 + v1 * v1 + v2 * v2;

    #pragma unroll
    for (int off = 16; off > 0; off >>= 1) {
        s += __shfl_xor_sync(0xFFFFFFFFu, s, off);
        q += __shfl_xor_sync(0xFFFFFFFFu, q, off);
    }
    __shared__ float ss[8], sq[8];
    const int wid = tid >> 5, lid = tid & 31;
    if (lid == 0) { ss[wid] = s; sq[wid] = q; }
    __syncthreads();
    if (tid == 0) {
        float S = 0.f, Q = 0.f;
        #pragma unroll
        for (int i = 0; i < 8; i++) { S += ss[i]; Q += sq[i]; }
        float m = S * (1.0f / DMODEL);
        float var = Q * (1.0f / DMODEL) - m * m;
        ss[0] = m;
        sq[0] = rsqrtf(var + 1e-5f);
    }
    __syncthreads();
    const float m = ss[0], r = sq[0];
    float o0 = (v0 - m) * r * w[tid]       + b[tid];
    float o1 = (v1 - m) * r * w[tid + 256] + b[tid + 256];
    float o2 = (v2 - m) * r * w[tid + 512] + b[tid + 512];
    yhr[tid]       = f2h(o0);
    yhr[tid + 256] = f2h(o1);
    yhr[tid + 512] = f2h(o2);
}

// ---------------- asm helpers ----------------
__device__ __forceinline__ unsigned smem_u32(const void* p)
{
    unsigned a;
    asm volatile("{ .reg .u64 t; cvta.to.shared.u64 t, %1; cvt.u32.u64 %0, t; }"
                 : "=r"(a) : "l"(p));
    return a;
}

__device__ __forceinline__ void ldsm4a(unsigned* r, unsigned addr)
{
    asm volatile("ldmatrix.sync.aligned.m8n8.x4.shared.b16 {%0,%1,%2,%3}, [%4];"
                 : "=r"(r[0]), "=r"(r[1]), "=r"(r[2]), "=r"(r[3]) : "r"(addr));
}

__device__ __forceinline__ void mma_f16(float* c, const unsigned* a, unsigned b0, unsigned b1)
{
    asm volatile("mma.sync.aligned.m16n8k16.row.col.f32.f16.f16.f32 "
                 "{%0,%1,%2,%3}, {%4,%5,%6,%7}, {%8,%9}, {%0,%1,%2,%3};"
                 : "+f"(c[0]), "+f"(c[1]), "+f"(c[2]), "+f"(c[3])
                 : "r"(a[0]), "r"(a[1]), "r"(a[2]), "r"(a[3]), "r"(b0), "r"(b1));
}

__device__ __forceinline__ void cp16(unsigned dst, const void* src)
{
    asm volatile("cp.async.cg.shared.global [%0], [%1], 16;"
                 :: "r"(dst), "l"(src) : "memory");
}

__device__ __forceinline__ void cp_commit()
{
    asm volatile("cp.async.commit_group;" ::: "memory");
}

__device__ __forceinline__ void cp_wait2()
{
    asm volatile("cp.async.wait_group 2;" ::: "memory");
}

__device__ __forceinline__ void cp_wait0()
{
    asm volatile("cp.async.wait_group 0;" ::: "memory");
}

// ---------------- Windowed attention (tensor-core, fp16, P aliased onto Q) --------
// One block per (window, head), 128 threads = 4 warps. Tiles padded to 64.
// smem: Q/P (aliased), K, Vt fp16 64x72-half rows (144B); S fp32 56x60.
#define HROWB 144
#define QOFF  0
#define POFF  0           // P overwrites Q after phase 1
#define KOFF  9216
#define VTOFF 18432
#define SOFF  27648
#define SSTR  60
#define ATTN_SMEM (27648 + 56 * SSTR * 4)   // 41088 bytes

__global__ __launch_bounds__(128) void attn_kernel(
    const unsigned short* __restrict__ qkv, unsigned short* __restrict__ oh)
{
    extern __shared__ unsigned char hsm[];
    const unsigned sbase = smem_u32(hsm);
    const int w  = blockIdx.x / NHEAD;
    const int hd = blockIdx.x % NHEAD;
    const int t0 = w * WS2;
    const int tid = threadIdx.x;
    const int lane = tid & 31;
    const int wi = tid >> 5;

    // zero the fp16 regions (Q, K, Vt = 27648 bytes = 1728 uint4)
    {
        uint4 z;
        z.x = 0; z.y = 0; z.z = 0; z.w = 0;
        for (int i = tid; i < 1728; i += 128)
            ((uint4*)hsm)[i] = z;
    }
    __syncthreads();

    // load q,k rows; v transposed (49 rows x 8 chunks of 8 halves)
    for (int i = tid; i < WS2 * 8; i += 128) {
        int r = i >> 3;
        int c8 = (i & 7) * 8;
        size_t base = (size_t)(t0 + r) * D3 + hd * DHEAD + c8;
        uint4 qu = *(const uint4*)(qkv + base);
        uint4 ku = *(const uint4*)(qkv + base + DMODEL);
        uint4 vu = *(const uint4*)(qkv + base + 2 * DMODEL);
        *(uint4*)(hsm + QOFF + r * HROWB + c8 * 2) = qu;
        *(uint4*)(hsm + KOFF + r * HROWB + c8 * 2) = ku;
        const unsigned short* vp = (const unsigned short*)&vu;
        #pragma unroll
        for (int e = 0; e < 8; e++)
            *(unsigned short*)(hsm + VTOFF + (c8 + e) * HROWB + r * 2) = vp[e];
    }
    __syncthreads();

    float* sS = (float*)(hsm + SOFF);

    // phase 1: S = Q @ K^T (warp wi: rows 16*wi..16*wi+15, all 64 cols)
    {
        float acc[8][4];
        #pragma unroll
        for (int i = 0; i < 8; i++)
            #pragma unroll
            for (int j = 0; j < 4; j++) acc[i][j] = 0.f;
        #pragma unroll
        for (int ks = 0; ks < 4; ks++) {
            unsigned aq[4];
            ldsm4a(aq, sbase + QOFF + (wi * 16 + (lane & 15)) * HROWB
                       + ks * 32 + ((lane >> 4) << 4));
            unsigned bk[4][4];
            #pragma unroll
            for (int nb = 0; nb < 4; nb++)
                ldsm4a(bk[nb], sbase + KOFF + (nb * 16 + (lane & 15)) * HROWB
                               + ks * 32 + ((lane >> 4) << 4));
            #pragma unroll
            for (int nt = 0; nt < 8; nt++)
                mma_f16(acc[nt], aq, bk[nt >> 1][nt & 1], bk[nt >> 1][(nt & 1) + 2]);
        }
        #pragma unroll
        for (int nt = 0; nt < 8; nt++) {
            #pragma unroll
            for (int half = 0; half < 2; half++) {
                int row = wi * 16 + (lane >> 2) + half * 8;
                int col = nt * 8 + (lane & 3) * 2;
                if (row < 56 && col < 56) {
                    sS[row * SSTR + col]     = acc[nt][half * 2 + 0] * 0.125f;
                    sS[row * SSTR + col + 1] = acc[nt][half * 2 + 1] * 0.125f;
                }
            }
        }
    }
    __syncthreads();

    // softmax (4 warps), write fp16 P over the dead Q region.
    // Explicitly zero padded cols (49..63) and padded rows (49..55).
    {
        unsigned short* sP = (unsigned short*)(hsm + POFF);
        for (int r = wi; r < 56; r += 4) {
            if (r < WS2) {
                float v1 = (lane < WS2)      ? sS[r * SSTR + lane]      : -1e30f;
                float v2 = (lane + 32 < WS2) ? sS[r * SSTR + 32 + lane] : -1e30f;
                float mx = fmaxf(v1, v2);
                #pragma unroll
                for (int off = 16; off > 0; off >>= 1)
                    mx = fmaxf(mx, __shfl_xor_sync(0xFFFFFFFFu, mx, off));
                float e1 = (lane < WS2)      ? __expf(v1 - mx) : 0.f;
                float e2 = (lane + 32 < WS2) ? __expf(v2 - mx) : 0.f;
                float sum = e1 + e2;
                #pragma unroll
                for (int off = 16; off > 0; off >>= 1)
                    sum += __shfl_xor_sync(0xFFFFFFFFu, sum, off);
                float inv = 1.0f / sum;
                sP[r * 72 + lane]      = (lane < WS2)      ? f2h(e1 * inv) : (unsigned short)0;
                sP[r * 72 + 32 + lane] = (lane + 32 < WS2) ? f2h(e2 * inv) : (unsigned short)0;
            } else {
                sP[r * 72 + lane]      = 0;
                sP[r * 72 + 32 + lane] = 0;
            }
        }
    }
    __syncthreads();

    // phase 2: O = P @ Vt^T (A = P [rows, j], B = Vt [d, j]; j padded with zeros)
    {
        float acc[8][4];
        #pragma unroll
        for (int i = 0; i < 8; i++)
            #pragma unroll
            for (int j = 0; j < 4; j++) acc[i][j] = 0.f;
        #pragma unroll
        for (int ks = 0; ks < 4; ks++) {
            unsigned ap[4];
            ldsm4a(ap, sbase + POFF + (wi * 16 + (lane & 15)) * HROWB
                       + ks * 32 + ((lane >> 4) << 4));
            unsigned bv[4][4];
            #pragma unroll
            for (int nb = 0; nb < 4; nb++)
                ldsm4a(bv[nb], sbase + VTOFF + (nb * 16 + (lane & 15)) * HROWB
                               + ks * 32 + ((lane >> 4) << 4));
            #pragma unroll
            for (int nt = 0; nt < 8; nt++)
                mma_f16(acc[nt], ap, bv[nt >> 1][nt & 1], bv[nt >> 1][(nt & 1) + 2]);
        }
        #pragma unroll
        for (int nt = 0; nt < 8; nt++) {
            #pragma unroll
            for (int half = 0; half < 2; half++) {
                int row = wi * 16 + (lane >> 2) + half * 8;
                int col = nt * 8 + (lane & 3) * 2;
                if (row < WS2) {
                    unsigned p = (unsigned)f2h(acc[nt][half * 2 + 0])
                               | ((unsigned)f2h(acc[nt][half * 2 + 1]) << 16);
                    *(unsigned*)(oh + (size_t)(t0 + row) * DMODEL + hd * DHEAD + col) = p;
                }
            }
        }
    }
}

// ---------------- fp16 tensor-core GEMM (cp.async 3-stage pipeline, K-chunk 32) ----
// C = act(A @ B^T + bias) (+ res); fp16 A [M,K], B [N,K]; block 128x128, K-chunk 32.
// 8 warps, warp tile 64x32, mma.m16n8k16.f16; smem rows 80B (64B data + 16B pad).
#define ROWB 80
#define PLANEB (128 * ROWB)          // 10240
#define STAGEB (2 * PLANEB)          // 20480 (A plane + B plane)
#define NSTAGE 3
#define SMEMB  (NSTAGE * STAGEB)     // 61440

template <bool GELU, bool RES, bool HALFOUT>
__global__ __launch_bounds__(256) void gemm_f16(
    const unsigned short* __restrict__ Ah,
    const unsigned short* __restrict__ Bh,
    const float* __restrict__ bias,
    const float* __restrict__ res,
    float* __restrict__ C,
    unsigned short* __restrict__ Ch,
    int N, int K)
{
    extern __shared__ unsigned char dsm[];
    const unsigned sbase = smem_u32(dsm);
    const int tid = threadIdx.x;
    const int lane = tid & 31;
    const int wid = tid >> 5;
    const int wm = wid & 1;
    const int wn = wid >> 1;
    const int bm = blockIdx.y * 128;
    const int bn = blockIdx.x * 128;

    float acc[4][4][4];
    #pragma unroll
    for (int i = 0; i < 4; i++)
        #pragma unroll
        for (int j = 0; j < 4; j++)
            #pragma unroll
            for (int k = 0; k < 4; k++) acc[i][j][k] = 0.f;

    // loader: rows r0 and r0+64, 16B chunk ch (8 halves) of the 64B k-chunk row
    const int r0 = tid >> 2;
    const int ch = tid & 3;
    const unsigned short* gA = Ah + (size_t)(bm + r0) * K + ch * 8;
    const unsigned short* gB = Bh + (size_t)(bn + r0) * K + ch * 8;
    const size_t rstep = (size_t)64 * K;
    const unsigned drow0 = r0 * ROWB + ch * 16;
    const unsigned drow1 = (r0 + 64) * ROWB + ch * 16;
    const int nkc = K / 32;

    // prologue: issue stages 0 and 1
    {
        const unsigned st = sbase;
        cp16(st + drow0,          gA);
        cp16(st + drow1,          gA + rstep);
        cp16(st + PLANEB + drow0, gB);
        cp16(st + PLANEB + drow1, gB + rstep);
        cp_commit();
        const unsigned st1 = sbase + STAGEB;
        cp16(st1 + drow0,          gA + 32);
        cp16(st1 + drow1,          gA + 32 + rstep);
        cp16(st1 + PLANEB + drow0, gB + 32);
        cp16(st1 + PLANEB + drow1, gB + 32 + rstep);
        cp_commit();
    }

    int stage = 0;
    for (int kc = 0; kc < nkc; kc++) {
        if (kc + 2 < nkc) {
            const int snext = (stage + 2 >= NSTAGE) ? (stage + 2 - NSTAGE) : (stage + 2);
            const unsigned st = sbase + snext * STAGEB;
            const int ko = (kc + 2) * 32;
            cp16(st + drow0,          gA + ko);
            cp16(st + drow1,          gA + ko + rstep);
            cp16(st + PLANEB + drow0, gB + ko);
            cp16(st + PLANEB + drow1, gB + ko + rstep);
            cp_commit();
            cp_wait2();
        } else {
            cp_wait0();
        }
        __syncthreads();

        const unsigned st = sbase + stage * STAGEB;
        #pragma unroll
        for (int ks = 0; ks < 2; ks++) {
            const unsigned abase = st + (wm * 64 + (lane & 15)) * ROWB
                                   + ks * 32 + ((lane >> 4) << 4);
            const unsigned bbase = st + PLANEB + (wn * 32 + (lane & 15)) * ROWB
                                   + ks * 32 + ((lane >> 4) << 4);
            unsigned ah[4][4];
            #pragma unroll
            for (int mi = 0; mi < 4; mi++)
                ldsm4a(ah[mi], abase + mi * 16 * ROWB);
            unsigned bh[2][4];
            #pragma unroll
            for (int nj = 0; nj < 2; nj++)
                ldsm4a(bh[nj], bbase + nj * 16 * ROWB);
            #pragma unroll
            for (int mi = 0; mi < 4; mi++)
                #pragma unroll
                for (int ni = 0; ni < 4; ni++)
                    mma_f16(acc[mi][ni], ah[mi], bh[ni >> 1][ni & 1],
                            bh[ni >> 1][(ni & 1) + 2]);
        }
        __syncthreads();
        stage = (stage + 1 >= NSTAGE) ? 0 : (stage + 1);
    }

    // epilogue
    #pragma unroll
    for (int mi = 0; mi < 4; mi++) {
        #pragma unroll
        for (int ni = 0; ni < 4; ni++) {
            const int col = bn + wn * 32 + ni * 8 + (lane & 3) * 2;
            const float bs0 = bias[col];
            const float bs1 = bias[col + 1];
            #pragma unroll
            for (int half = 0; half < 2; half++) {
                const int row = bm + wm * 64 + mi * 16 + (lane >> 2) + half * 8;
                float v0 = acc[mi][ni][half * 2 + 0] + bs0;
                float v1 = acc[mi][ni][half * 2 + 1] + bs1;
                if (GELU) {
                    v0 = 0.5f * v0 * (1.0f + erff(v0 * 0.70710678118654752f));
                    v1 = 0.5f * v1 * (1.0f + erff(v1 * 0.70710678118654752f));
                }
                if (RES) {
                    float2 r2 = *(const float2*)(res + (size_t)row * N + col);
                    v0 += r2.x;
                    v1 += r2.y;
                }
                if (HALFOUT) {
                    unsigned p = (unsigned)f2h(v0) | ((unsigned)f2h(v1) << 16);
                    *(unsigned*)(Ch + (size_t)row * N + col) = p;
                } else {
                    float2 o2;
                    o2.x = v0;
                    o2.y = v1;
                    *(float2*)(C + (size_t)row * N + col) = o2;
                }
            }
        }
    }
}

// ---------------- host-side launch ----------------
extern "C" void kernel_launch(void* const* d_in, const int* in_sizes, int n_in,
                              void* d_out, int out_size)
{
    const float* x     = (const float*)d_in[0];
    const float* Wqkv  = (const float*)d_in[1];
    const float* bqkv  = (const float*)d_in[2];
    const float* Wo    = (const float*)d_in[3];
    const float* bo    = (const float*)d_in[4];
    const float* ln1_w = (const float*)d_in[5];
    const float* ln1_b = (const float*)d_in[6];
    const float* W1    = (const float*)d_in[7];
    const float* b1    = (const float*)d_in[8];
    const float* W2    = (const float*)d_in[9];
    const float* b2    = (const float*)d_in[10];
    const float* ln2_w = (const float*)d_in[11];
    const float* ln2_b = (const float*)d_in[12];
    float* out = (float*)d_out;

    static float *p_h = nullptr;
    static unsigned short *p_qkvh = nullptr, *p_yh = nullptr, *p_oh = nullptr;
    static unsigned short *p_fh = nullptr, *p_wh = nullptr;
    if (!p_h) {
        cudaGetSymbolAddress((void**)&p_h,    g_h);
        cudaGetSymbolAddress((void**)&p_qkvh, g_qkvh);
        cudaGetSymbolAddress((void**)&p_yh,   g_yh);
        cudaGetSymbolAddress((void**)&p_oh,   g_oh);
        cudaGetSymbolAddress((void**)&p_fh,   g_fh);
        cudaGetSymbolAddress((void**)&p_wh,   g_wh);
        cudaFuncSetAttribute(gemm_f16<false, false, true>,
                             cudaFuncAttributeMaxDynamicSharedMemorySize, SMEMB);
        cudaFuncSetAttribute(gemm_f16<false, true, false>,
                             cudaFuncAttributeMaxDynamicSharedMemorySize, SMEMB);
        cudaFuncSetAttribute(gemm_f16<true, false, true>,
                             cudaFuncAttributeMaxDynamicSharedMemorySize, SMEMB);
        cudaFuncSetAttribute(attn_kernel,
                             cudaFuncAttributeMaxDynamicSharedMemorySize, ATTN_SMEM);
    }

    const dim3 blk(256);
    const dim3 ablk(128);
    const dim3 grid_qkv(D3 / 128,     T_TOKENS / 128);
    const dim3 grid_d  (DMODEL / 128, T_TOKENS / 128);
    const dim3 grid_ff (FFDIM / 128,  T_TOKENS / 128);

    for (int l = 0; l < 2; l++) {
        const float* hin  = (l == 0) ? x : p_h;
        float* hout2 = (l == 1) ? out : p_h;   // last FFN GEMM writes final output

        // pre-norm attention
        ln_kernel<<<T_TOKENS, blk>>>(hin, ln1_w + l * DMODEL, ln1_b + l * DMODEL, p_yh);
        cvt_kernel<<<(D3 * DMODEL) / 1024, blk>>>(Wqkv + (size_t)l * D3 * DMODEL, p_wh);
        gemm_f16<false, false, true><<<grid_qkv, blk, SMEMB>>>(
            p_yh, p_wh, bqkv + (size_t)l * D3,
            nullptr, nullptr, p_qkvh, D3, DMODEL);
        attn_kernel<<<NWIN * NHEAD, ablk, ATTN_SMEM>>>(p_qkvh, p_oh);
        cvt_kernel<<<(DMODEL * DMODEL) / 1024, blk>>>(Wo + (size_t)l * DMODEL * DMODEL, p_wh);
        gemm_f16<false, true, false><<<grid_d, blk, SMEMB>>>(
            p_oh, p_wh, bo + (size_t)l * DMODEL,
            hin, p_h, nullptr, DMODEL, DMODEL);

        // pre-norm FFN
        ln_kernel<<<T_TOKENS, blk>>>(p_h, ln2_w + l * DMODEL, ln2_b + l * DMODEL, p_yh);
        cvt_kernel<<<(FFDIM * DMODEL) / 1024, blk>>>(W1 + (size_t)l * FFDIM * DMODEL, p_wh);
        gemm_f16<true, false, true><<<grid_ff, blk, SMEMB>>>(
            p_yh, p_wh, b1 + (size_t)l * FFDIM,
            nullptr, nullptr, p_fh, FFDIM, DMODEL);
        cvt_kernel<<<(DMODEL * FFDIM) / 1024, blk>>>(W2 + (size_t)l * DMODEL * FFDIM, p_wh);
        gemm_f16<false, true, false><<<grid_d, blk, SMEMB>>>(
            p_fh, p_wh, b2 + (size_t)l * DMODEL,
            p_h, hout2, nullptr, DMODEL, FFDIM);
    }
    (void)in_sizes; (void)n_in; (void)out_size;
}